// round 16
// baseline (speedup 1.0000x reference)
#include <cuda_runtime.h>
#include <math.h>
#include <cstdint>

#define T_    512
#define B_    64
#define IN_   256
#define H_    1024
#define H3_   3072
#define OUT_  50257

#define NB    128         // gru consumer blocks
#define NW    24          // gi producer blocks
#define WPAD  516         // padded word stride per (gate,slot) slice
#define MTG_D 3142        // ceil(50257/16) col tiles for dense
#define DBLK  393

// ---------------- device scratch ----------------
__device__ float g_gi[(size_t)T_ * B_ * H3_];    // [T][B][3H]
__device__ uint4 g_wfrag[64 * 3 * 64 * 32 * 2];  // W_hh frags
__device__ uint4 g_hfrag[2][8 * 64 * 32];        // h frags, double-buffered
__device__ uint4 g_wihfrag[192 * 16 * 64];       // W_ih frags
__device__ uint4 g_xfrag[(size_t)4096 * 16 * 32];// x frags
__device__ uint4 g_wdfrag[(size_t)MTG_D * 64 * 64]; // W_dense frags
__device__ float g_bhh[H3_];
__device__ unsigned g_ready[T_];                 // gi[t] completion (target NW)
__device__ unsigned g_sub2[2][8 * 32];
__device__ unsigned g_master2[2 * 32];
__device__ unsigned g_phase2[2 * 32];

typedef unsigned long long u64;

static __device__ __forceinline__ float sigmoidf_(float x){ return 1.0f / (1.0f + expf(-x)); }
static __device__ __forceinline__ float tanhf_(float x){
    float e = expf(-2.0f * fabsf(x));
    float t = (1.0f - e) / (1.0f + e);
    return copysignf(t, x);
}

static __device__ __forceinline__ unsigned f2bf(float f){
    unsigned u = __float_as_uint(f);
    unsigned r = u + 0x7FFFu + ((u >> 16) & 1u);
    return (r >> 16) & 0xFFFFu;
}
static __device__ __forceinline__ float bf2f(unsigned s){
    return __uint_as_float(s << 16);
}
static __device__ __forceinline__ unsigned pack_bf2(float a, float b){
    return f2bf(a) | (f2bf(b) << 16);
}

#define MMA_BF16(C, A, b0v, b1v) \
    asm volatile("mma.sync.aligned.m16n8k16.row.col.f32.bf16.bf16.f32 " \
        "{%0,%1,%2,%3}, {%4,%5,%6,%7}, {%8,%9}, {%0,%1,%2,%3};" \
        : "+f"((C)[0]), "+f"((C)[1]), "+f"((C)[2]), "+f"((C)[3]) \
        : "r"((A).x), "r"((A).y), "r"((A).z), "r"((A).w), "r"(b0v), "r"(b1v))

// ---------------- init ----------------
__global__ void init_kernel(){
    int i = blockIdx.x * blockDim.x + threadIdx.x;
    if (i < 8 * 64 * 32){
        g_hfrag[0][i] = make_uint4(0u, 0u, 0u, 0u);
        g_hfrag[1][i] = make_uint4(0u, 0u, 0u, 0u);
    }
    if (i < T_) g_ready[i] = 0u;
    if (i < 8 * 32){ g_sub2[0][i] = 0u; g_sub2[1][i] = 0u; }
    if (i < 2 * 32){ g_master2[i] = 0u; g_phase2[i] = 0u; }
}

__global__ void bhh_copy_kernel(const float* __restrict__ bhh){
    int i = blockIdx.x * 256 + threadIdx.x;
    if (i < H3_) g_bhh[i] = bhh[i];
}

// ---------------- W_hh -> fragment layout ----------------
__global__ void wfrag_kernel(const float* __restrict__ Whh){
    int gid = blockIdx.x * 256 + threadIdx.x;
    int lane = gid & 31;
    int tile = gid >> 5;
    if (tile >= 64 * 3 * 64) return;
    int ktg = tile & 63;
    int mt  = (tile >> 6) % 3;
    int cg  = tile / 192;
    int c0  = cg * 16;
    int row0 = mt * H_ + c0;
    int j = lane >> 2;
    int k = ktg * 16 + (lane & 3) * 2;

    const float* W = Whh;
    float w00 = W[(size_t)(row0 + j    ) * H_ + k    ];
    float w01 = W[(size_t)(row0 + j    ) * H_ + k + 1];
    float w10 = W[(size_t)(row0 + j + 8) * H_ + k    ];
    float w11 = W[(size_t)(row0 + j + 8) * H_ + k + 1];
    float w02 = W[(size_t)(row0 + j    ) * H_ + k + 8];
    float w03 = W[(size_t)(row0 + j    ) * H_ + k + 9];
    float w12 = W[(size_t)(row0 + j + 8) * H_ + k + 8];
    float w13 = W[(size_t)(row0 + j + 8) * H_ + k + 9];

    uint4 hi, lo;
    hi.x = pack_bf2(w00, w01); hi.y = pack_bf2(w10, w11);
    hi.z = pack_bf2(w02, w03); hi.w = pack_bf2(w12, w13);
    lo.x = pack_bf2(w00 - bf2f(f2bf(w00)), w01 - bf2f(f2bf(w01)));
    lo.y = pack_bf2(w10 - bf2f(f2bf(w10)), w11 - bf2f(f2bf(w11)));
    lo.z = pack_bf2(w02 - bf2f(f2bf(w02)), w03 - bf2f(f2bf(w03)));
    lo.w = pack_bf2(w12 - bf2f(f2bf(w12)), w13 - bf2f(f2bf(w13)));

    g_wfrag[(size_t)tile * 64 + lane * 2    ] = hi;
    g_wfrag[(size_t)tile * 64 + lane * 2 + 1] = lo;
}

// ---------------- W_ih -> fragment layout ----------------
__global__ void wihfrag_kernel(const float* __restrict__ Wih){
    int gid = blockIdx.x * 256 + threadIdx.x;
    int lane = gid & 31;
    int tile = gid >> 5;
    if (tile >= 192 * 16) return;
    int ktg = tile & 15;
    int mtg = tile >> 4;
    int row0 = mtg * 16;
    int j = lane >> 2;
    int k = ktg * 16 + (lane & 3) * 2;

    const float* W = Wih;
    float w00 = W[(size_t)(row0 + j    ) * IN_ + k    ];
    float w01 = W[(size_t)(row0 + j    ) * IN_ + k + 1];
    float w10 = W[(size_t)(row0 + j + 8) * IN_ + k    ];
    float w11 = W[(size_t)(row0 + j + 8) * IN_ + k + 1];
    float w02 = W[(size_t)(row0 + j    ) * IN_ + k + 8];
    float w03 = W[(size_t)(row0 + j    ) * IN_ + k + 9];
    float w12 = W[(size_t)(row0 + j + 8) * IN_ + k + 8];
    float w13 = W[(size_t)(row0 + j + 8) * IN_ + k + 9];

    uint4 hi, lo;
    hi.x = pack_bf2(w00, w01); hi.y = pack_bf2(w10, w11);
    hi.z = pack_bf2(w02, w03); hi.w = pack_bf2(w12, w13);
    lo.x = pack_bf2(w00 - bf2f(f2bf(w00)), w01 - bf2f(f2bf(w01)));
    lo.y = pack_bf2(w10 - bf2f(f2bf(w10)), w11 - bf2f(f2bf(w11)));
    lo.z = pack_bf2(w02 - bf2f(f2bf(w02)), w03 - bf2f(f2bf(w03)));
    lo.w = pack_bf2(w12 - bf2f(f2bf(w12)), w13 - bf2f(f2bf(w13)));

    g_wihfrag[(size_t)tile * 64 + lane * 2    ] = hi;
    g_wihfrag[(size_t)tile * 64 + lane * 2 + 1] = lo;
}

// ---------------- x -> B-fragment layout ----------------
__global__ void xfrag_kernel(const float* __restrict__ x){
    int gid = blockIdx.x * 256 + threadIdx.x;
    int lane = gid & 31;
    int t16 = gid >> 5;
    if (t16 >= 4096 * 16) return;
    int ktg = t16 & 15;
    int nt  = t16 >> 4;
    int n = nt * 8 + (lane >> 2);
    int k = ktg * 16 + (lane & 3) * 2;
    int b = n & 63;
    int t = n >> 6;
    const float* xr = x + ((size_t)b * T_ + t) * IN_;
    float f0 = xr[k], f1 = xr[k + 1], f2 = xr[k + 8], f3 = xr[k + 9];
    uint4 v;
    v.x = pack_bf2(f0, f1);
    v.y = pack_bf2(f2, f3);
    v.z = pack_bf2(f0 - bf2f(f2bf(f0)), f1 - bf2f(f2bf(f1)));
    v.w = pack_bf2(f2 - bf2f(f2bf(f2)), f3 - bf2f(f2bf(f3)));
    g_xfrag[(size_t)t16 * 32 + lane] = v;
}

// ---------------- gi producer task (one (mtg-quad, nt-quad) tile) ----------------
static __device__ __forceinline__ void gi_task(int mtg, int ntb, const float* __restrict__ bih, int l){
    float C[4][4];
    #pragma unroll
    for (int q = 0; q < 4; q++)
        #pragma unroll
        for (int r = 0; r < 4; r++) C[q][r] = 0.0f;

    #pragma unroll 4
    for (int ktg = 0; ktg < 16; ktg++){
        size_t ai = ((size_t)mtg * 16 + ktg) * 64 + l * 2;
        uint4 Ah = g_wihfrag[ai];
        uint4 Al = g_wihfrag[ai + 1];
        uint4 Bv[4];
        #pragma unroll
        for (int q = 0; q < 4; q++)
            Bv[q] = g_xfrag[((size_t)(ntb + q) * 16 + ktg) * 32 + l];
        #pragma unroll
        for (int q = 0; q < 4; q++){
            MMA_BF16(C[q], Ah, Bv[q].x, Bv[q].y);
            MMA_BF16(C[q], Ah, Bv[q].z, Bv[q].w);
            MMA_BF16(C[q], Al, Bv[q].x, Bv[q].y);
        }
    }

    const int col0 = mtg * 16 + (l >> 2);
    const int col1 = col0 + 8;
    const float b0 = bih[col0];
    const float b1 = bih[col1];
    #pragma unroll
    for (int q = 0; q < 4; q++){
        int n = (ntb + q) * 8 + (l & 3) * 2;
        g_gi[(size_t)n       * H3_ + col0] = C[q][0] + b0;
        g_gi[(size_t)(n + 1) * H3_ + col0] = C[q][1] + b0;
        g_gi[(size_t)n       * H3_ + col1] = C[q][2] + b1;
        g_gi[(size_t)(n + 1) * H3_ + col1] = C[q][3] + b1;
    }
}

// ---------------- per-half two-level grid barrier (gru blocks only) ----------------
static __device__ __forceinline__ void grid_bar(int tid, int blk, unsigned target){
    __syncthreads();
    if (tid == 0){
        const int half = blk & 1;
        const int grp  = (blk >> 1) >> 3;
        unsigned a;
        asm volatile("atom.acq_rel.gpu.global.add.u32 %0, [%1], %2;"
                     : "=r"(a) : "l"(&g_sub2[half][grp * 32]), "r"(1u) : "memory");
        bool released = false;
        if (a + 1u == 8u * target){
            unsigned m;
            asm volatile("atom.acq_rel.gpu.global.add.u32 %0, [%1], %2;"
                         : "=r"(m) : "l"(&g_master2[half * 32]), "r"(1u) : "memory");
            if (m + 1u == 8u * target){
                asm volatile("st.release.gpu.global.u32 [%0], %1;"
                             :: "l"(&g_phase2[half * 32]), "r"(target) : "memory");
                released = true;
            }
        }
        if (!released){
            unsigned pcur;
            do {
                asm volatile("ld.acquire.gpu.global.u32 %0, [%1];"
                             : "=r"(pcur) : "l"(&g_phase2[half * 32]) : "memory");
            } while (pcur < target);
        }
    }
    __syncthreads();
}

// ---------------- fused persistent kernel: 128 gru consumers + 24 gi producers ----------------
__global__ __launch_bounds__(256, 1) void gru_fused(const float* __restrict__ bih,
                                                    const float* __restrict__ Wd)
{
    extern __shared__ float red[];   // [3 gates][4 slots][WPAD]

    const int tid = threadIdx.x;
    const int w   = tid >> 5;
    const int l   = tid & 31;
    const int blk = blockIdx.x;

    if (blk >= NB){
        // ================= gi producer =================
        const int wk = blk - NB;                 // 0..23
        const int mtg_base = (wk * 2) * 4 + (w >> 1);
        #pragma unroll 1
        for (int t = 0; t < T_; t++){
            const int ntb = t * 8 + (w & 1) * 4;
            gi_task(mtg_base,     ntb, bih, l);
            gi_task(mtg_base + 4, ntb, bih, l);
            __threadfence();
            __syncthreads();
            if (tid == 0){
                unsigned dummy;
                asm volatile("atom.acq_rel.gpu.global.add.u32 %0, [%1], %2;"
                             : "=r"(dummy) : "l"(&g_ready[t]), "r"(1u) : "memory");
            }
        }
        // ---- then convert W_dense fragments (consumed by dense_mma afterwards) ----
        for (int gid = wk * 256 + tid; gid < MTG_D * 64 * 32; gid += NW * 256){
            int lane = gid & 31;
            int tile = gid >> 5;
            int ktg = tile & 63;
            int mtg = tile >> 6;
            int row0 = mtg * 16;
            int j = lane >> 2;
            int k = ktg * 16 + (lane & 3) * 2;
            int r0 = row0 + j;
            int r1 = row0 + j + 8;
            bool ok0 = (r0 < OUT_);
            bool ok1 = (r1 < OUT_);
            const float* W0 = Wd + (size_t)(ok0 ? r0 : 0) * H_;
            const float* W1 = Wd + (size_t)(ok1 ? r1 : 0) * H_;
            float w00 = ok0 ? W0[k    ] : 0.f;
            float w01 = ok0 ? W0[k + 1] : 0.f;
            float w02 = ok0 ? W0[k + 8] : 0.f;
            float w03 = ok0 ? W0[k + 9] : 0.f;
            float w10 = ok1 ? W1[k    ] : 0.f;
            float w11 = ok1 ? W1[k + 1] : 0.f;
            float w12 = ok1 ? W1[k + 8] : 0.f;
            float w13 = ok1 ? W1[k + 9] : 0.f;
            uint4 hi, lo;
            hi.x = pack_bf2(w00, w01); hi.y = pack_bf2(w10, w11);
            hi.z = pack_bf2(w02, w03); hi.w = pack_bf2(w12, w13);
            lo.x = pack_bf2(w00 - bf2f(f2bf(w00)), w01 - bf2f(f2bf(w01)));
            lo.y = pack_bf2(w10 - bf2f(f2bf(w10)), w11 - bf2f(f2bf(w11)));
            lo.z = pack_bf2(w02 - bf2f(f2bf(w02)), w03 - bf2f(f2bf(w03)));
            lo.w = pack_bf2(w12 - bf2f(f2bf(w12)), w13 - bf2f(f2bf(w13)));
            g_wdfrag[(size_t)tile * 64 + lane * 2    ] = hi;
            g_wdfrag[(size_t)tile * 64 + lane * 2 + 1] = lo;
        }
        return;
    }

    // ================= gru consumer =================
    const int cg  = blk >> 1;
    const int c0  = cg * 16;
    const int nb0 = (blk & 1) * 32;
    const int ntb = (blk & 1) * 4;

    const int gntl = tid >> 6;
    const int grem = tid & 63;
    const int gjj  = grem >> 3;
    const int gnc  = grem & 7;
    const int gn   = nb0 + gntl * 8 + gnc;
    const int lane_r = gjj * 4 + (gnc >> 1);
    const int rp   = gnc & 1;

    const float bhr0 = g_bhh[c0 + gjj];
    const float bhr1 = g_bhh[c0 + gjj + 8];
    const float bhz0 = g_bhh[H_ + c0 + gjj];
    const float bhz1 = g_bhh[H_ + c0 + gjj + 8];
    const float bhn0 = g_bhh[2 * H_ + c0 + gjj];
    const float bhn1 = g_bhh[2 * H_ + c0 + gjj + 8];

    float hold0 = 0.0f;
    float hold1 = 0.0f;

    const uint4* wf = g_wfrag;
    unsigned bar_t = 0;

    #pragma unroll 1
    for (int t = 0; t < T_; t++){
        const uint4* hfr = g_hfrag[t & 1];
        uint4* hfw4 = &g_hfrag[(t + 1) & 1][0];

        float C[3][4][4];
        #pragma unroll
        for (int mt = 0; mt < 3; mt++)
            #pragma unroll
            for (int nt = 0; nt < 4; nt++)
                #pragma unroll
                for (int r = 0; r < 4; r++) C[mt][nt][r] = 0.0f;

        // ---- MMA phase: B double-buffered one kt ahead ----
        uint4 Bv[2][4];
        {
            const int ktg0 = w * 8;
            #pragma unroll
            for (int nt = 0; nt < 4; nt++)
                Bv[0][nt] = __ldcg(&hfr[(size_t)((ntb + nt) * 64 + ktg0) * 32 + l]);
        }
        #pragma unroll
        for (int kt = 0; kt < 8; kt++){
            const int ktg = w * 8 + kt;
            const int cur = kt & 1;
            if (kt < 7){
                #pragma unroll
                for (int nt = 0; nt < 4; nt++)
                    Bv[cur ^ 1][nt] = __ldcg(&hfr[(size_t)((ntb + nt) * 64 + ktg + 1) * 32 + l]);
            }
            uint4 Ah[3], Al[3];
            #pragma unroll
            for (int mt = 0; mt < 3; mt++){
                size_t ti = ((size_t)(cg * 3 + mt) * 64 + ktg) * 64 + l * 2;
                Ah[mt] = wf[ti];
                Al[mt] = wf[ti + 1];
            }
            #pragma unroll
            for (int mt = 0; mt < 3; mt++){
                #pragma unroll
                for (int nt = 0; nt < 4; nt++){
                    MMA_BF16(C[mt][nt], Ah[mt], Bv[cur][nt].x, Bv[cur][nt].y);
                    MMA_BF16(C[mt][nt], Ah[mt], Bv[cur][nt].z, Bv[cur][nt].w);
                    MMA_BF16(C[mt][nt], Al[mt], Bv[cur][nt].x, Bv[cur][nt].y);
                }
            }
        }

        // ---- phase 1: warps 4-7 store partials; tid0 waits for gi[t] ready ----
        if (w >= 4){
            #pragma unroll
            for (int mt = 0; mt < 3; mt++){
                #pragma unroll
                for (int nt = 0; nt < 4; nt++){
                    int wordu = (mt * 4 + (w - 4)) * WPAD + (nt * 32 + l) * 4;
                    *(float4*)&red[wordu] = make_float4(C[mt][nt][0], C[mt][nt][1],
                                                        C[mt][nt][2], C[mt][nt][3]);
                }
            }
        } else if (tid == 0){
            unsigned rv;
            do {
                asm volatile("ld.acquire.gpu.global.u32 %0, [%1];"
                             : "=r"(rv) : "l"(&g_ready[t]) : "memory");
            } while (rv < (unsigned)NW);
        }
        __syncthreads();

        // ---- gi loads (now guaranteed ready), interleaved with phase 2 RMW ----
        const float* gA = g_gi + ((size_t)t * B_ + gn) * H3_ + c0 + gjj;
        float gir0 = __ldcg(gA),          gir1 = __ldcg(gA + 8);
        float giz0 = __ldcg(gA + H_),     giz1 = __ldcg(gA + H_ + 8);
        float gin0 = __ldcg(gA + 2 * H_), gin1 = __ldcg(gA + 2 * H_ + 8);

        if (w < 4){
            #pragma unroll
            for (int mt = 0; mt < 3; mt++){
                #pragma unroll
                for (int nt = 0; nt < 4; nt++){
                    int wordu = (mt * 4 + w) * WPAD + (nt * 32 + l) * 4;
                    float4 v = *(const float4*)&red[wordu];
                    v.x += C[mt][nt][0]; v.y += C[mt][nt][1];
                    v.z += C[mt][nt][2]; v.w += C[mt][nt][3];
                    *(float4*)&red[wordu] = v;
                }
            }
        }
        __syncthreads();

        // ---- final reduce over 4 slots + gates ----
        float gh0[3], gh1[3];
        #pragma unroll
        for (int g = 0; g < 3; g++){
            float4 s = make_float4(0.f, 0.f, 0.f, 0.f);
            #pragma unroll
            for (int sv = 0; sv < 4; sv++){
                float4 v = *(const float4*)&red[(g * 4 + sv) * WPAD + (gntl * 32 + lane_r) * 4];
                s.x += v.x; s.y += v.y; s.z += v.z; s.w += v.w;
            }
            gh0[g] = rp ? s.y : s.x;
            gh1[g] = rp ? s.w : s.z;
        }

        float r0 = sigmoidf_(gir0 + gh0[0] + bhr0);
        float z0 = sigmoidf_(giz0 + gh0[1] + bhz0);
        float n0 = tanhf_(gin0 + r0 * (gh0[2] + bhn0));
        float hn0 = (1.0f - z0) * n0 + z0 * hold0;
        hold0 = hn0;

        float r1 = sigmoidf_(gir1 + gh1[0] + bhr1);
        float z1 = sigmoidf_(giz1 + gh1[1] + bhz1);
        float n1 = tanhf_(gin1 + r1 * (gh1[2] + bhn1));
        float hn1 = (1.0f - z1) * n1 + z1 * hold1;
        hold1 = hn1;

        {
            unsigned x0 = f2bf(hn0);
            unsigned x1 = f2bf(hn0 - bf2f(x0));
            unsigned x2 = f2bf(hn1);
            unsigned x3 = f2bf(hn1 - bf2f(x2));
            unsigned p0 = __shfl_xor_sync(0xffffffffu, x0, 8);
            unsigned p1 = __shfl_xor_sync(0xffffffffu, x1, 8);
            unsigned p2 = __shfl_xor_sync(0xffffffffu, x2, 8);
            unsigned p3 = __shfl_xor_sync(0xffffffffu, x3, 8);
            if ((gjj & 1) == 0){
                int lb = gnc * 4 + (gjj >> 1);
                uint4 v;
                v.x = x0 | (p0 << 16);
                v.y = x2 | (p2 << 16);
                v.z = x1 | (p1 << 16);
                v.w = x3 | (p3 << 16);
                hfw4[((size_t)(ntb + gntl) * 64 + cg) * 32 + lb] = v;
            }
        }

        bar_t += 1u;
        grid_bar(tid, blk, bar_t);
    }
}

// ---------------- logits via HMMA: out = h @ Wd^T + bd ----------------
__global__ __launch_bounds__(256) void dense_mma(const float* __restrict__ bd,
                                                 float* __restrict__ out)
{
    const int tid = threadIdx.x;
    const int w = tid >> 5;
    const int l = tid & 31;
    const int mtg = blockIdx.x * 8 + w;
    if (mtg >= MTG_D) return;

    float C[8][4];
    #pragma unroll
    for (int q = 0; q < 8; q++)
        #pragma unroll
        for (int r = 0; r < 4; r++) C[q][r] = 0.0f;

    #pragma unroll 2
    for (int ktg = 0; ktg < 64; ktg++){
        size_t ai = ((size_t)mtg * 64 + ktg) * 64 + l * 2;
        uint4 Ah = g_wdfrag[ai];
        uint4 Al = g_wdfrag[ai + 1];
        #pragma unroll
        for (int q = 0; q < 8; q++){
            uint4 Bv = g_hfrag[0][(size_t)(q * 64 + ktg) * 32 + l];
            MMA_BF16(C[q], Ah, Bv.x, Bv.y);
            MMA_BF16(C[q], Ah, Bv.z, Bv.w);
            MMA_BF16(C[q], Al, Bv.x, Bv.y);
        }
    }

    const int col0 = mtg * 16 + (l >> 2);
    const int col1 = col0 + 8;
    const bool ok0 = (col0 < OUT_);
    const bool ok1 = (col1 < OUT_);
    const float b0 = ok0 ? bd[col0] : 0.f;
    const float b1 = ok1 ? bd[col1] : 0.f;
    #pragma unroll
    for (int q = 0; q < 8; q++){
        int n = q * 8 + (l & 3) * 2;
        if (ok0){
            out[(size_t)n       * OUT_ + col0] = C[q][0] + b0;
            out[(size_t)(n + 1) * OUT_ + col0] = C[q][1] + b0;
        }
        if (ok1){
            out[(size_t)n       * OUT_ + col1] = C[q][2] + b1;
            out[(size_t)(n + 1) * OUT_ + col1] = C[q][3] + b1;
        }
    }
}

// ---------------- in-place row-wise log_softmax ----------------
__global__ __launch_bounds__(256) void lsm_kernel(float* __restrict__ out)
{
    __shared__ float red[256];
    const int tid = threadIdx.x;
    float* row = out + (size_t)blockIdx.x * OUT_;

    float m = -1e30f;
    for (int i = tid; i < OUT_; i += 256) m = fmaxf(m, row[i]);
    red[tid] = m; __syncthreads();
    for (int s = 128; s > 0; s >>= 1){
        if (tid < s) red[tid] = fmaxf(red[tid], red[tid + s]);
        __syncthreads();
    }
    float M = red[0];
    __syncthreads();

    float sm = 0.0f;
    for (int i = tid; i < OUT_; i += 256) sm += expf(row[i] - M);
    red[tid] = sm; __syncthreads();
    for (int s = 128; s > 0; s >>= 1){
        if (tid < s) red[tid] += red[tid + s];
        __syncthreads();
    }
    float L = M + logf(red[0]);
    for (int i = tid; i < OUT_; i += 256) row[i] -= L;
}

// ---------------- launch ----------------
extern "C" void kernel_launch(void* const* d_in, const int* in_sizes, int n_in,
                              void* d_out, int out_size)
{
    const float* x    = (const float*)d_in[0];
    const float* Wih  = (const float*)d_in[1];
    const float* Whh  = (const float*)d_in[2];
    const float* bih  = (const float*)d_in[3];
    const float* bhh  = (const float*)d_in[4];
    const float* Wd   = (const float*)d_in[5];
    const float* bd   = (const float*)d_in[6];
    float* out = (float*)d_out;

    const size_t smem_bytes = (size_t)3 * 4 * WPAD * sizeof(float);  // 24768
    cudaFuncSetAttribute(gru_fused, cudaFuncAttributeMaxDynamicSharedMemorySize,
                         (int)smem_bytes);

    init_kernel<<<64, 1024>>>();
    bhh_copy_kernel<<<(H3_ + 255) / 256, 256>>>(bhh);
    wfrag_kernel<<<1536, 256>>>(Whh);
    wihfrag_kernel<<<384, 256>>>(Wih);
    xfrag_kernel<<<8192, 256>>>(x);
    gru_fused<<<NB + NW, 256, smem_bytes>>>(bih, Wd);
    dense_mma<<<DBLK, 256>>>(bd, out);
    lsm_kernel<<<B_, 256>>>(out);
}

// round 17
// speedup vs baseline: 1.2427x; 1.2427x over previous
#include <cuda_runtime.h>
#include <math.h>
#include <cstdint>

#define T_    512
#define B_    64
#define IN_   256
#define H_    1024
#define H3_   3072
#define OUT_  50257

#define NB    128         // persistent blocks; block = 16 cols x 32 batches
#define WPAD  516         // padded word stride per (gate,slot) slice
#define MTG_D 3142        // ceil(50257/16) col tiles for dense
#define DBLK  393

// ---------------- device scratch ----------------
__device__ float g_gi[(size_t)T_ * B_ * H3_];    // [T][B][3H]
__device__ uint4 g_wfrag[64 * 3 * 64 * 32 * 2];  // W_hh frags
__device__ uint4 g_hfrag[2][8 * 64 * 32];        // h frags, double-buffered
__device__ uint4 g_wihfrag[192 * 16 * 64];       // W_ih frags
__device__ uint4 g_xfrag[(size_t)4096 * 16 * 32];// x frags
__device__ uint4 g_wdfrag[(size_t)MTG_D * 64 * 64]; // W_dense frags
__device__ float g_bhh[H3_];
__device__ unsigned g_sub2[2][8 * 32];
__device__ unsigned g_master2[2 * 32];
__device__ unsigned g_phase2[2 * 32];

typedef unsigned long long u64;

static __device__ __forceinline__ float sigmoidf_(float x){ return 1.0f / (1.0f + expf(-x)); }
static __device__ __forceinline__ float tanhf_(float x){
    float e = expf(-2.0f * fabsf(x));
    float t = (1.0f - e) / (1.0f + e);
    return copysignf(t, x);
}

static __device__ __forceinline__ unsigned f2bf(float f){
    unsigned u = __float_as_uint(f);
    unsigned r = u + 0x7FFFu + ((u >> 16) & 1u);
    return (r >> 16) & 0xFFFFu;
}
static __device__ __forceinline__ float bf2f(unsigned s){
    return __uint_as_float(s << 16);
}
static __device__ __forceinline__ unsigned pack_bf2(float a, float b){
    return f2bf(a) | (f2bf(b) << 16);
}

#define MMA_BF16(C, A, b0v, b1v) \
    asm volatile("mma.sync.aligned.m16n8k16.row.col.f32.bf16.bf16.f32 " \
        "{%0,%1,%2,%3}, {%4,%5,%6,%7}, {%8,%9}, {%0,%1,%2,%3};" \
        : "+f"((C)[0]), "+f"((C)[1]), "+f"((C)[2]), "+f"((C)[3]) \
        : "r"((A).x), "r"((A).y), "r"((A).z), "r"((A).w), "r"(b0v), "r"(b1v))

// ---------------- init ----------------
__global__ void init_kernel(){
    int i = blockIdx.x * blockDim.x + threadIdx.x;
    if (i < 8 * 64 * 32){
        g_hfrag[0][i] = make_uint4(0u, 0u, 0u, 0u);
        g_hfrag[1][i] = make_uint4(0u, 0u, 0u, 0u);
    }
    if (i < 8 * 32){ g_sub2[0][i] = 0u; g_sub2[1][i] = 0u; }
    if (i < 2 * 32){ g_master2[i] = 0u; g_phase2[i] = 0u; }
}

__global__ void bhh_copy_kernel(const float* __restrict__ bhh){
    int i = blockIdx.x * 256 + threadIdx.x;
    if (i < H3_) g_bhh[i] = bhh[i];
}

// ---------------- W_hh -> fragment layout ----------------
__global__ void wfrag_kernel(const float* __restrict__ Whh){
    int gid = blockIdx.x * 256 + threadIdx.x;
    int lane = gid & 31;
    int tile = gid >> 5;
    if (tile >= 64 * 3 * 64) return;
    int ktg = tile & 63;
    int mt  = (tile >> 6) % 3;
    int cg  = tile / 192;
    int c0  = cg * 16;
    int row0 = mt * H_ + c0;
    int j = lane >> 2;
    int k = ktg * 16 + (lane & 3) * 2;

    const float* W = Whh;
    float w00 = W[(size_t)(row0 + j    ) * H_ + k    ];
    float w01 = W[(size_t)(row0 + j    ) * H_ + k + 1];
    float w10 = W[(size_t)(row0 + j + 8) * H_ + k    ];
    float w11 = W[(size_t)(row0 + j + 8) * H_ + k + 1];
    float w02 = W[(size_t)(row0 + j    ) * H_ + k + 8];
    float w03 = W[(size_t)(row0 + j    ) * H_ + k + 9];
    float w12 = W[(size_t)(row0 + j + 8) * H_ + k + 8];
    float w13 = W[(size_t)(row0 + j + 8) * H_ + k + 9];

    uint4 hi, lo;
    hi.x = pack_bf2(w00, w01); hi.y = pack_bf2(w10, w11);
    hi.z = pack_bf2(w02, w03); hi.w = pack_bf2(w12, w13);
    lo.x = pack_bf2(w00 - bf2f(f2bf(w00)), w01 - bf2f(f2bf(w01)));
    lo.y = pack_bf2(w10 - bf2f(f2bf(w10)), w11 - bf2f(f2bf(w11)));
    lo.z = pack_bf2(w02 - bf2f(f2bf(w02)), w03 - bf2f(f2bf(w03)));
    lo.w = pack_bf2(w12 - bf2f(f2bf(w12)), w13 - bf2f(f2bf(w13)));

    g_wfrag[(size_t)tile * 64 + lane * 2    ] = hi;
    g_wfrag[(size_t)tile * 64 + lane * 2 + 1] = lo;
}

// ---------------- W_ih -> fragment layout ----------------
__global__ void wihfrag_kernel(const float* __restrict__ Wih){
    int gid = blockIdx.x * 256 + threadIdx.x;
    int lane = gid & 31;
    int tile = gid >> 5;
    if (tile >= 192 * 16) return;
    int ktg = tile & 15;
    int mtg = tile >> 4;
    int row0 = mtg * 16;
    int j = lane >> 2;
    int k = ktg * 16 + (lane & 3) * 2;

    const float* W = Wih;
    float w00 = W[(size_t)(row0 + j    ) * IN_ + k    ];
    float w01 = W[(size_t)(row0 + j    ) * IN_ + k + 1];
    float w10 = W[(size_t)(row0 + j + 8) * IN_ + k    ];
    float w11 = W[(size_t)(row0 + j + 8) * IN_ + k + 1];
    float w02 = W[(size_t)(row0 + j    ) * IN_ + k + 8];
    float w03 = W[(size_t)(row0 + j    ) * IN_ + k + 9];
    float w12 = W[(size_t)(row0 + j + 8) * IN_ + k + 8];
    float w13 = W[(size_t)(row0 + j + 8) * IN_ + k + 9];

    uint4 hi, lo;
    hi.x = pack_bf2(w00, w01); hi.y = pack_bf2(w10, w11);
    hi.z = pack_bf2(w02, w03); hi.w = pack_bf2(w12, w13);
    lo.x = pack_bf2(w00 - bf2f(f2bf(w00)), w01 - bf2f(f2bf(w01)));
    lo.y = pack_bf2(w10 - bf2f(f2bf(w10)), w11 - bf2f(f2bf(w11)));
    lo.z = pack_bf2(w02 - bf2f(f2bf(w02)), w03 - bf2f(f2bf(w03)));
    lo.w = pack_bf2(w12 - bf2f(f2bf(w12)), w13 - bf2f(f2bf(w13)));

    g_wihfrag[(size_t)tile * 64 + lane * 2    ] = hi;
    g_wihfrag[(size_t)tile * 64 + lane * 2 + 1] = lo;
}

// ---------------- W_dense -> fragment layout (row-guarded) ----------------
__global__ void wdfrag_kernel(const float* __restrict__ Wd){
    int gid = blockIdx.x * 256 + threadIdx.x;
    int lane = gid & 31;
    int tile = gid >> 5;
    if (tile >= MTG_D * 64) return;
    int ktg = tile & 63;
    int mtg = tile >> 6;
    int row0 = mtg * 16;
    int j = lane >> 2;
    int k = ktg * 16 + (lane & 3) * 2;
    int r0 = row0 + j;
    int r1 = row0 + j + 8;
    bool ok0 = (r0 < OUT_);
    bool ok1 = (r1 < OUT_);

    const float* W0 = Wd + (size_t)(ok0 ? r0 : 0) * H_;
    const float* W1 = Wd + (size_t)(ok1 ? r1 : 0) * H_;
    float w00 = ok0 ? W0[k    ] : 0.f;
    float w01 = ok0 ? W0[k + 1] : 0.f;
    float w02 = ok0 ? W0[k + 8] : 0.f;
    float w03 = ok0 ? W0[k + 9] : 0.f;
    float w10 = ok1 ? W1[k    ] : 0.f;
    float w11 = ok1 ? W1[k + 1] : 0.f;
    float w12 = ok1 ? W1[k + 8] : 0.f;
    float w13 = ok1 ? W1[k + 9] : 0.f;

    uint4 hi, lo;
    hi.x = pack_bf2(w00, w01); hi.y = pack_bf2(w10, w11);
    hi.z = pack_bf2(w02, w03); hi.w = pack_bf2(w12, w13);
    lo.x = pack_bf2(w00 - bf2f(f2bf(w00)), w01 - bf2f(f2bf(w01)));
    lo.y = pack_bf2(w10 - bf2f(f2bf(w10)), w11 - bf2f(f2bf(w11)));
    lo.z = pack_bf2(w02 - bf2f(f2bf(w02)), w03 - bf2f(f2bf(w03)));
    lo.w = pack_bf2(w12 - bf2f(f2bf(w12)), w13 - bf2f(f2bf(w13)));

    g_wdfrag[(size_t)tile * 64 + lane * 2    ] = hi;
    g_wdfrag[(size_t)tile * 64 + lane * 2 + 1] = lo;
}

// ---------------- x -> B-fragment layout ----------------
__global__ void xfrag_kernel(const float* __restrict__ x){
    int gid = blockIdx.x * 256 + threadIdx.x;
    int lane = gid & 31;
    int t16 = gid >> 5;
    if (t16 >= 4096 * 16) return;
    int ktg = t16 & 15;
    int nt  = t16 >> 4;
    int n = nt * 8 + (lane >> 2);
    int k = ktg * 16 + (lane & 3) * 2;
    int b = n & 63;
    int t = n >> 6;
    const float* xr = x + ((size_t)b * T_ + t) * IN_;
    float f0 = xr[k], f1 = xr[k + 1], f2 = xr[k + 8], f3 = xr[k + 9];
    uint4 v;
    v.x = pack_bf2(f0, f1);
    v.y = pack_bf2(f2, f3);
    v.z = pack_bf2(f0 - bf2f(f2bf(f0)), f1 - bf2f(f2bf(f1)));
    v.w = pack_bf2(f2 - bf2f(f2bf(f2)), f3 - bf2f(f2bf(f3)));
    g_xfrag[(size_t)t16 * 32 + lane] = v;
}

// ---------------- GI via HMMA ----------------
__global__ __launch_bounds__(256) void gi_mma(const float* __restrict__ bih){
    const int tid = threadIdx.x;
    const int w = tid >> 5;
    const int l = tid & 31;
    const int mtg = blockIdx.y * 4 + (w >> 1);
    const int ntb = blockIdx.x * 8 + (w & 1) * 4;

    float C[4][4];
    #pragma unroll
    for (int q = 0; q < 4; q++)
        #pragma unroll
        for (int r = 0; r < 4; r++) C[q][r] = 0.0f;

    #pragma unroll 4
    for (int ktg = 0; ktg < 16; ktg++){
        size_t ai = ((size_t)mtg * 16 + ktg) * 64 + l * 2;
        uint4 Ah = g_wihfrag[ai];
        uint4 Al = g_wihfrag[ai + 1];
        uint4 Bv[4];
        #pragma unroll
        for (int q = 0; q < 4; q++)
            Bv[q] = g_xfrag[((size_t)(ntb + q) * 16 + ktg) * 32 + l];
        #pragma unroll
        for (int q = 0; q < 4; q++){
            MMA_BF16(C[q], Ah, Bv[q].x, Bv[q].y);
            MMA_BF16(C[q], Ah, Bv[q].z, Bv[q].w);
            MMA_BF16(C[q], Al, Bv[q].x, Bv[q].y);
        }
    }

    const int col0 = mtg * 16 + (l >> 2);
    const int col1 = col0 + 8;
    const float b0 = bih[col0];
    const float b1 = bih[col1];
    #pragma unroll
    for (int q = 0; q < 4; q++){
        int n = (ntb + q) * 8 + (l & 3) * 2;
        g_gi[(size_t)n       * H3_ + col0] = C[q][0] + b0;
        g_gi[(size_t)(n + 1) * H3_ + col0] = C[q][1] + b0;
        g_gi[(size_t)n       * H3_ + col1] = C[q][2] + b1;
        g_gi[(size_t)(n + 1) * H3_ + col1] = C[q][3] + b1;
    }
}

// ---------------- split grid barrier: arrive / wait ----------------
static __device__ __forceinline__ void grid_arrive(int tid, int blk, unsigned target){
    __syncthreads();   // all warps done with h-frag writeback
    if (tid == 0){
        const int half = blk & 1;
        const int grp  = (blk >> 1) >> 3;
        unsigned a;
        asm volatile("atom.acq_rel.gpu.global.add.u32 %0, [%1], %2;"
                     : "=r"(a) : "l"(&g_sub2[half][grp * 32]), "r"(1u) : "memory");
        if (a + 1u == 8u * target){
            unsigned m;
            asm volatile("atom.acq_rel.gpu.global.add.u32 %0, [%1], %2;"
                         : "=r"(m) : "l"(&g_master2[half * 32]), "r"(1u) : "memory");
            if (m + 1u == 8u * target){
                asm volatile("st.release.gpu.global.u32 [%0], %1;"
                             :: "l"(&g_phase2[half * 32]), "r"(target) : "memory");
            }
        }
    }
}

static __device__ __forceinline__ void grid_wait(int tid, int blk, unsigned target){
    if (tid == 0){
        const int half = blk & 1;
        unsigned pcur;
        do {
            asm volatile("ld.acquire.gpu.global.u32 %0, [%1];"
                         : "=r"(pcur) : "l"(&g_phase2[half * 32]) : "memory");
        } while (pcur < target);
    }
    __syncthreads();
}

// ---------------- persistent HMMA recurrence ----------------
__global__ __launch_bounds__(256, 1) void gru_mma()
{
    extern __shared__ float red[];   // [3 gates][4 slots][WPAD]

    const int tid = threadIdx.x;
    const int w   = tid >> 5;
    const int l   = tid & 31;
    const int blk = blockIdx.x;
    const int cg  = blk >> 1;
    const int c0  = cg * 16;
    const int nb0 = (blk & 1) * 32;
    const int ntb = (blk & 1) * 4;

    const int gntl = tid >> 6;
    const int grem = tid & 63;
    const int gjj  = grem >> 3;
    const int gnc  = grem & 7;
    const int gn   = nb0 + gntl * 8 + gnc;
    const int lane_r = gjj * 4 + (gnc >> 1);
    const int rp   = gnc & 1;

    const float bhr0 = g_bhh[c0 + gjj];
    const float bhr1 = g_bhh[c0 + gjj + 8];
    const float bhz0 = g_bhh[H_ + c0 + gjj];
    const float bhz1 = g_bhh[H_ + c0 + gjj + 8];
    const float bhn0 = g_bhh[2 * H_ + c0 + gjj];
    const float bhn1 = g_bhh[2 * H_ + c0 + gjj + 8];

    float hold0 = 0.0f;
    float hold1 = 0.0f;

    const uint4* wf = g_wfrag;
    unsigned bar_t = 0;

    // prologue: prefetch gi[0] (L2-only; keep W frags in L1)
    const float* gA0 = g_gi + (size_t)gn * H3_ + c0 + gjj;
    float gir0 = __ldcg(gA0),          gir1 = __ldcg(gA0 + 8);
    float giz0 = __ldcg(gA0 + H_),     giz1 = __ldcg(gA0 + H_ + 8);
    float gin0 = __ldcg(gA0 + 2 * H_), gin1 = __ldcg(gA0 + 2 * H_ + 8);

    #pragma unroll 1
    for (int t = 0; t < T_; t++){
        const uint4* hfr = g_hfrag[t & 1];
        uint4* hfw4 = &g_hfrag[(t + 1) & 1][0];

        float C[3][4][4];
        #pragma unroll
        for (int mt = 0; mt < 3; mt++)
            #pragma unroll
            for (int nt = 0; nt < 4; nt++)
                #pragma unroll
                for (int r = 0; r < 4; r++) C[mt][nt][r] = 0.0f;

        // ---- MMA phase: B double-buffered one kt ahead ----
        uint4 Bv[2][4];
        {
            const int ktg0 = w * 8;
            #pragma unroll
            for (int nt = 0; nt < 4; nt++)
                Bv[0][nt] = __ldcg(&hfr[(size_t)((ntb + nt) * 64 + ktg0) * 32 + l]);
        }
        #pragma unroll
        for (int kt = 0; kt < 8; kt++){
            const int ktg = w * 8 + kt;
            const int cur = kt & 1;
            if (kt < 7){
                #pragma unroll
                for (int nt = 0; nt < 4; nt++)
                    Bv[cur ^ 1][nt] = __ldcg(&hfr[(size_t)((ntb + nt) * 64 + ktg + 1) * 32 + l]);
            }
            uint4 Ah[3], Al[3];
            #pragma unroll
            for (int mt = 0; mt < 3; mt++){
                size_t ti = ((size_t)(cg * 3 + mt) * 64 + ktg) * 64 + l * 2;
                Ah[mt] = wf[ti];
                Al[mt] = wf[ti + 1];
            }
            #pragma unroll
            for (int mt = 0; mt < 3; mt++){
                #pragma unroll
                for (int nt = 0; nt < 4; nt++){
                    MMA_BF16(C[mt][nt], Ah[mt], Bv[cur][nt].x, Bv[cur][nt].y);
                    MMA_BF16(C[mt][nt], Ah[mt], Bv[cur][nt].z, Bv[cur][nt].w);
                    MMA_BF16(C[mt][nt], Al[mt], Bv[cur][nt].x, Bv[cur][nt].y);
                }
            }
        }

        // ---- two-phase reduction ----
        if (w >= 4){
            #pragma unroll
            for (int mt = 0; mt < 3; mt++){
                #pragma unroll
                for (int nt = 0; nt < 4; nt++){
                    int wordu = (mt * 4 + (w - 4)) * WPAD + (nt * 32 + l) * 4;
                    *(float4*)&red[wordu] = make_float4(C[mt][nt][0], C[mt][nt][1],
                                                        C[mt][nt][2], C[mt][nt][3]);
                }
            }
        }
        __syncthreads();
        if (w < 4){
            #pragma unroll
            for (int mt = 0; mt < 3; mt++){
                #pragma unroll
                for (int nt = 0; nt < 4; nt++){
                    int wordu = (mt * 4 + w) * WPAD + (nt * 32 + l) * 4;
                    float4 v = *(const float4*)&red[wordu];
                    v.x += C[mt][nt][0]; v.y += C[mt][nt][1];
                    v.z += C[mt][nt][2]; v.w += C[mt][nt][3];
                    *(float4*)&red[wordu] = v;
                }
            }
        }
        __syncthreads();

        // ---- final reduce over 4 slots + gates ----
        float gh0[3], gh1[3];
        #pragma unroll
        for (int g = 0; g < 3; g++){
            float4 s = make_float4(0.f, 0.f, 0.f, 0.f);
            #pragma unroll
            for (int sv = 0; sv < 4; sv++){
                float4 v = *(const float4*)&red[(g * 4 + sv) * WPAD + (gntl * 32 + lane_r) * 4];
                s.x += v.x; s.y += v.y; s.z += v.z; s.w += v.w;
            }
            gh0[g] = rp ? s.y : s.x;
            gh1[g] = rp ? s.w : s.z;
        }

        float r0 = sigmoidf_(gir0 + gh0[0] + bhr0);
        float z0 = sigmoidf_(giz0 + gh0[1] + bhz0);
        float n0 = tanhf_(gin0 + r0 * (gh0[2] + bhn0));
        float hn0 = (1.0f - z0) * n0 + z0 * hold0;
        hold0 = hn0;

        float r1 = sigmoidf_(gir1 + gh1[0] + bhr1);
        float z1 = sigmoidf_(giz1 + gh1[1] + bhz1);
        float n1 = tanhf_(gin1 + r1 * (gh1[2] + bhn1));
        float hn1 = (1.0f - z1) * n1 + z1 * hold1;
        hold1 = hn1;

        {
            unsigned x0 = f2bf(hn0);
            unsigned x1 = f2bf(hn0 - bf2f(x0));
            unsigned x2 = f2bf(hn1);
            unsigned x3 = f2bf(hn1 - bf2f(x2));
            unsigned p0 = __shfl_xor_sync(0xffffffffu, x0, 8);
            unsigned p1 = __shfl_xor_sync(0xffffffffu, x1, 8);
            unsigned p2 = __shfl_xor_sync(0xffffffffu, x2, 8);
            unsigned p3 = __shfl_xor_sync(0xffffffffu, x3, 8);
            if ((gjj & 1) == 0){
                int lb = gnc * 4 + (gjj >> 1);
                uint4 v;
                v.x = x0 | (p0 << 16);
                v.y = x2 | (p2 << 16);
                v.z = x1 | (p1 << 16);
                v.w = x3 | (p3 << 16);
                hfw4[((size_t)(ntb + gntl) * 64 + cg) * 32 + lb] = v;
            }
        }

        // ---- arrive; prefetch gi[t+1] under barrier latency; wait ----
        bar_t += 1u;
        grid_arrive(tid, blk, bar_t);
        if (t + 1 < T_){
            const float* gA = g_gi + ((size_t)(t + 1) * B_ + gn) * H3_ + c0 + gjj;
            gir0 = __ldcg(gA);          gir1 = __ldcg(gA + 8);
            giz0 = __ldcg(gA + H_);     giz1 = __ldcg(gA + H_ + 8);
            gin0 = __ldcg(gA + 2 * H_); gin1 = __ldcg(gA + 2 * H_ + 8);
        }
        grid_wait(tid, blk, bar_t);
    }
}

// ---------------- logits via HMMA: out = h @ Wd^T + bd ----------------
__global__ __launch_bounds__(256) void dense_mma(const float* __restrict__ bd,
                                                 float* __restrict__ out)
{
    const int tid = threadIdx.x;
    const int w = tid >> 5;
    const int l = tid & 31;
    const int mtg = blockIdx.x * 8 + w;
    if (mtg >= MTG_D) return;

    float C[8][4];
    #pragma unroll
    for (int q = 0; q < 8; q++)
        #pragma unroll
        for (int r = 0; r < 4; r++) C[q][r] = 0.0f;

    #pragma unroll 2
    for (int ktg = 0; ktg < 64; ktg++){
        size_t ai = ((size_t)mtg * 64 + ktg) * 64 + l * 2;
        uint4 Ah = g_wdfrag[ai];
        uint4 Al = g_wdfrag[ai + 1];
        #pragma unroll
        for (int q = 0; q < 8; q++){
            uint4 Bv = g_hfrag[0][(size_t)(q * 64 + ktg) * 32 + l];
            MMA_BF16(C[q], Ah, Bv.x, Bv.y);
            MMA_BF16(C[q], Ah, Bv.z, Bv.w);
            MMA_BF16(C[q], Al, Bv.x, Bv.y);
        }
    }

    const int col0 = mtg * 16 + (l >> 2);
    const int col1 = col0 + 8;
    const bool ok0 = (col0 < OUT_);
    const bool ok1 = (col1 < OUT_);
    const float b0 = ok0 ? bd[col0] : 0.f;
    const float b1 = ok1 ? bd[col1] : 0.f;
    #pragma unroll
    for (int q = 0; q < 8; q++){
        int n = q * 8 + (l & 3) * 2;
        if (ok0){
            out[(size_t)n       * OUT_ + col0] = C[q][0] + b0;
            out[(size_t)(n + 1) * OUT_ + col0] = C[q][1] + b0;
        }
        if (ok1){
            out[(size_t)n       * OUT_ + col1] = C[q][2] + b1;
            out[(size_t)(n + 1) * OUT_ + col1] = C[q][3] + b1;
        }
    }
}

// ---------------- in-place row-wise log_softmax ----------------
__global__ __launch_bounds__(256) void lsm_kernel(float* __restrict__ out)
{
    __shared__ float red[256];
    const int tid = threadIdx.x;
    float* row = out + (size_t)blockIdx.x * OUT_;

    float m = -1e30f;
    for (int i = tid; i < OUT_; i += 256) m = fmaxf(m, row[i]);
    red[tid] = m; __syncthreads();
    for (int s = 128; s > 0; s >>= 1){
        if (tid < s) red[tid] = fmaxf(red[tid], red[tid + s]);
        __syncthreads();
    }
    float M = red[0];
    __syncthreads();

    float sm = 0.0f;
    for (int i = tid; i < OUT_; i += 256) sm += expf(row[i] - M);
    red[tid] = sm; __syncthreads();
    for (int s = 128; s > 0; s >>= 1){
        if (tid < s) red[tid] += red[tid + s];
        __syncthreads();
    }
    float L = M + logf(red[0]);
    for (int i = tid; i < OUT_; i += 256) row[i] -= L;
}

// ---------------- launch ----------------
extern "C" void kernel_launch(void* const* d_in, const int* in_sizes, int n_in,
                              void* d_out, int out_size)
{
    const float* x    = (const float*)d_in[0];
    const float* Wih  = (const float*)d_in[1];
    const float* Whh  = (const float*)d_in[2];
    const float* bih  = (const float*)d_in[3];
    const float* bhh  = (const float*)d_in[4];
    const float* Wd   = (const float*)d_in[5];
    const float* bd   = (const float*)d_in[6];
    float* out = (float*)d_out;

    const size_t smem_bytes = (size_t)3 * 4 * WPAD * sizeof(float);  // 24768
    cudaFuncSetAttribute(gru_mma, cudaFuncAttributeMaxDynamicSharedMemorySize,
                         (int)smem_bytes);

    init_kernel<<<64, 1024>>>();
    bhh_copy_kernel<<<(H3_ + 255) / 256, 256>>>(bhh);
    wfrag_kernel<<<1536, 256>>>(Whh);
    wihfrag_kernel<<<384, 256>>>(Wih);
    wdfrag_kernel<<<(MTG_D * 64 * 32 + 255) / 256, 256>>>(Wd);
    xfrag_kernel<<<8192, 256>>>(x);
    gi_mma<<<dim3(512, 48), 256>>>(bih);
    gru_mma<<<NB, 256, smem_bytes>>>();
    dense_mma<<<DBLK, 256>>>(bd, out);
    lsm_kernel<<<B_, 256>>>(out);
}